// round 8
// baseline (speedup 1.0000x reference)
#include <cuda_runtime.h>
#include <cstdint>

// LatentDT: z[n,v] = clamp(min over edges on root->v path of +-(x[n].A[s]), 0, 1)
// Pruned DFS visits ~DEPTH+1 splits per row.
//
// R8 (= R7 resubmit; infra failure last round): split into
// (1) pure float4 memset of out at max write bandwidth, and
// (2) a tiny DFS scatter kernel writing only the ~11 surviving values/row.
// Total float count 32768*2047 is divisible by 4 -> exact float4 memset.

#define DEPTH     10
#define NB_SPLIT  1023   // 2^10 - 1
#define NB_NODES  2047   // 2^11 - 1
#define KDIM      128

// ---------------- Kernel 1: pure zero fill (canonical write-BW kernel) ----
__global__ void __launch_bounds__(256) zerofill_kernel(float4* __restrict__ out4,
                                                       int n4)
{
    const float4 z4 = make_float4(0.f, 0.f, 0.f, 0.f);
    const int stride = gridDim.x * blockDim.x;
    for (int i = blockIdx.x * blockDim.x + threadIdx.x; i < n4; i += stride)
        out4[i] = z4;
}

// ---------------- Kernel 2: warp-per-row pruned DFS, sparse scatter --------
__global__ void __launch_bounds__(256, 8) latentdt_scatter_kernel(
    const float* __restrict__ x,
    const float* __restrict__ A,
    float* __restrict__ out,
    int rows)
{
    const int row  = (blockIdx.x * blockDim.x + threadIdx.x) >> 5;
    const int lane = threadIdx.x & 31;
    if (row >= rows) return;

    // x row: 128 floats, 4 per lane (coalesced).
    const float4 xv = __ldg(reinterpret_cast<const float4*>(
                                x + (size_t)row * KDIM) + lane);

    float* outrow = out + (size_t)row * NB_NODES;
    if (lane == 0) outrow[0] = 1.0f;        // root: clamp(1) = 1

    // Warp-uniform lazy DFS: all lanes keep identical (node, q, stack).
    int   st_node[DEPTH + 1];
    float st_q[DEPTH + 1];
    int   sp   = 0;
    int   node = 0;
    float q    = 1.0f;

    while (true) {
        // dot(x_row, A[node]): per-lane float4 FMA + butterfly reduce
        const float4 av = __ldg(reinterpret_cast<const float4*>(
                                    A + (size_t)node * KDIM) + lane);
        float p = fmaf(xv.x, av.x,
                  fmaf(xv.y, av.y,
                  fmaf(xv.z, av.z, xv.w * av.w)));
        p += __shfl_xor_sync(0xffffffffu, p, 16);
        p += __shfl_xor_sync(0xffffffffu, p, 8);
        p += __shfl_xor_sync(0xffffffffu, p, 4);
        p += __shfl_xor_sync(0xffffffffu, p, 2);
        p += __shfl_xor_sync(0xffffffffu, p, 1);
        // p warp-uniform now.

        const float qL = fminf(q, p);       // always <= 1 (q starts at 1)
        const float qR = fminf(q, -p);
        const int cl = 2 * node + 1;        // left child; cl+1 = right child

        if (lane == 0) {
            if (qL > 0.0f) outrow[cl]     = qL;
            if (qR > 0.0f) outrow[cl + 1] = qR;
        }

        const bool childIsSplit = (cl < NB_SPLIT);
        const bool goL = childIsSplit && (qL > 0.0f);
        const bool goR = childIsSplit && (qR > 0.0f);

        if (goL) {
            if (goR) { st_node[sp] = cl + 1; st_q[sp] = qR; ++sp; }
            node = cl;  q = qL;
        } else if (goR) {
            node = cl + 1;  q = qR;
        } else {
            if (sp == 0) break;
            --sp;
            node = st_node[sp];  q = st_q[sp];
        }
    }
}

extern "C" void kernel_launch(void* const* d_in, const int* in_sizes, int n_in,
                              void* d_out, int out_size)
{
    const float* x = (const float*)d_in[0];   // [rows, 128]
    const float* A = (const float*)d_in[1];   // [1023, 128]
    float* out = (float*)d_out;               // [rows, 2047]

    const int rows = out_size / NB_NODES;     // 32768

    // Kernel 1: exact float4 memset (out_size = rows*2047 divisible by 4).
    const int n4 = out_size >> 2;
    zerofill_kernel<<<2048, 256>>>(reinterpret_cast<float4*>(out), n4);

    // Kernel 2: pruned DFS scatter (runs after fill in-stream).
    const int threads = 256;                  // 8 warps/block, 1 row/warp
    const int blocks = (rows + 7) / 8;
    latentdt_scatter_kernel<<<blocks, threads>>>(x, A, out, rows);
}

// round 9
// speedup vs baseline: 1.4123x; 1.4123x over previous
#include <cuda_runtime.h>

// LatentDT: z[n,v] = clamp(min over edges on root->v path of +-(x[n].A[s]), 0, 1)
// KEY: at a live split (q>0), qL>0 iff p>0 and qR>0 iff p<0 -> exactly ONE
// child survives each level. The "tree DFS" is a single root-to-leaf path:
// stackless, exactly DEPTH levels, 11 writes per row.
// Kernel is output-write-bandwidth bound (~5.0 TB/s measured ceiling).

#define DEPTH     10
#define NB_SPLIT  1023   // 2^10 - 1
#define NB_NODES  2047   // 2^11 - 1
#define KDIM      128

__global__ void __launch_bounds__(256, 8) latentdt_kernel(
    const float* __restrict__ x,
    const float* __restrict__ A,
    float* __restrict__ out,
    int rows)
{
    const int row  = (blockIdx.x * blockDim.x + threadIdx.x) >> 5;
    const int lane = threadIdx.x & 31;
    if (row >= rows) return;

    // x row: 128 floats, 4 per lane (512B, coalesced).
    const float4 xv = __ldg(reinterpret_cast<const float4*>(
                                x + (size_t)row * KDIM) + lane);

    const float4* __restrict__ Af4 = reinterpret_cast<const float4*>(A);

    // Prefetch A[0] so the root dot's load latency hides under the fill.
    float4 av = __ldg(Af4 + lane);

    float* outrow = out + (size_t)row * NB_NODES;

    // Per-warp scalar zero fill of own row (measured-best variant).
    for (int idx = lane; idx < NB_NODES; idx += 32) outrow[idx] = 0.0f;
    __syncwarp();                      // order fill before scatter overwrites
    if (lane == 0) outrow[0] = 1.0f;   // root: clamp(1) = 1

    // ---- Stackless path descent: exactly one survivor per level ----
    int   node = 0;
    float q    = 1.0f;                 // path-min, always > 0 while looping

    #pragma unroll
    for (int d = 0; d < DEPTH; ++d) {
        // dot(x_row, A[node]): per-lane float4 FMA + butterfly reduce
        float p = fmaf(xv.x, av.x,
                  fmaf(xv.y, av.y,
                  fmaf(xv.z, av.z, xv.w * av.w)));
        p += __shfl_xor_sync(0xffffffffu, p, 16);
        p += __shfl_xor_sync(0xffffffffu, p, 8);
        p += __shfl_xor_sync(0xffffffffu, p, 4);
        p += __shfl_xor_sync(0xffffffffu, p, 2);
        p += __shfl_xor_sync(0xffffffffu, p, 1);
        // p warp-uniform.

        if (p > 0.0f) {                        // left child survives
            const int cl = 2 * node + 1;
            q = fminf(q, p);                   // <= 1 always
            if (lane == 0) outrow[cl] = q;
            node = cl;
        } else if (p < 0.0f) {                 // right child survives
            const int cr = 2 * node + 2;
            q = fminf(q, -p);
            if (lane == 0) outrow[cr] = q;
            node = cr;
        } else {
            break;                             // p == 0: both children clamp to 0
        }

        if (d < DEPTH - 1)                     // load next level's A row
            av = __ldg(Af4 + (size_t)node * (KDIM / 4) + lane);
    }
}

extern "C" void kernel_launch(void* const* d_in, const int* in_sizes, int n_in,
                              void* d_out, int out_size)
{
    const float* x = (const float*)d_in[0];   // [rows, 128]
    const float* A = (const float*)d_in[1];   // [1023, 128]
    float* out = (float*)d_out;               // [rows, 2047]

    const int rows = out_size / NB_NODES;     // 32768

    const int threads = 256;                  // 8 warps/block, 1 row/warp
    const int blocks = (rows + 7) / 8;
    latentdt_kernel<<<blocks, threads>>>(x, A, out, rows);
}